// round 12
// baseline (speedup 1.0000x reference)
#include <cuda_runtime.h>

typedef unsigned long long ull;

#define CIN   6
#define COUT  16
#define HT    512
#define WD    512

#define TX    8           // threads.x
#define TY    16          // threads.y = tile height
#define PXT   8           // pixels per thread
#define TW    (TX*PXT)    // 64
#define TH    TY          // 16
#define SH    (TH+4)      // 20 halo rows
#define SPR   84          // swizzled pair row: i(k)=k+2*(k>>3)
#define NT    256
#define NTILE (8*32*32)   // 8192 tiles
#define NCTA  296         // 148 SMs * 2 CTAs
#define NTASK (SH*17)     // 340 build tasks per channel
#define NT2   (NTASK-NT)  // 84 threads carry a second task

__device__ __forceinline__ ull pk(float lo, float hi) {
    ull r; asm("mov.b64 %0,{%1,%2};" : "=l"(r) : "f"(lo), "f"(hi)); return r;
}
__device__ __forceinline__ ull fma2(ull a, ull b, ull c) {
    ull d; asm("fma.rn.f32x2 %0,%1,%2,%3;" : "=l"(d) : "l"(a), "l"(b), "l"(c)); return d;
}

// Balanced 2-coloring of the C3 table: every cin has exactly 5 live couts per half.
// half 0: {1,2,4,5,6,8,10,15}   half 1: {0,3,7,9,11,12,13,14}
__device__ const int d_LIVEG[2][CIN][5] = {
  {{4,5,6,10,15},{1,5,6,10,15},{1,2,6,8,15},{1,2,6,8,15},{2,4,8,10,15},{4,5,8,10,15}},
  {{0,9,11,12,14},{0,7,11,12,13},{0,7,11,13,14},{3,7,9,12,14},{3,7,9,12,13},{3,9,11,13,14}}};
__device__ constexpr int LIVEL[2][CIN][5] = {
  {{2,3,4,6,7},{0,3,4,6,7},{0,1,4,5,7},{0,1,4,5,7},{1,2,5,6,7},{2,3,5,6,7}},
  {{0,3,4,5,7},{0,2,4,5,6},{0,2,4,6,7},{1,2,3,5,7},{1,2,3,5,6},{1,3,4,6,7}}};
__device__ constexpr int HC[2][8] = {{1,2,4,5,6,8,10,15},{0,3,7,9,11,12,13,14}};

#define NWSM (2*CIN*5*5*6)   // [half][cin][dy][jj][dx pad6] = 1800 ulls

struct Smem {
    ull   sp[2][SH][SPR];   // 2-slot channel ring of interleaved pair rows (26.9 KB)
    ull   wsm[NWSM];        // duplicated weight pairs (14.4 KB)
    float sb[COUT];
};

struct Task { float t0, t1, t2, t3, t4; };

// Fetch taps t[4q..4q+4] of (channel c, halo row) — t[i] = x col (w0-2+i).
__device__ __forceinline__ void fetch_task(
    const float* __restrict__ xb, int c, int h0, int w0, int u, Task& T)
{
    int row = u / 17;
    int q   = u - row * 17;
    int gr  = h0 - 2 + row;
    T.t0 = T.t1 = T.t2 = T.t3 = T.t4 = 0.0f;
    if ((unsigned)gr < HT) {
        const float* rowp = xb + (size_t)c * HT * WD + (size_t)gr * WD;
        int ca = w0 - 4 + 4 * q;          // covers t[4q-2 .. 4q+5] via 2 LDG.128
        if (ca >= 0 && ca + 7 < WD) {
            float4 A4 = *reinterpret_cast<const float4*>(rowp + ca);
            float4 B4 = *reinterpret_cast<const float4*>(rowp + ca + 4);
            T.t0 = A4.z; T.t1 = A4.w; T.t2 = B4.x; T.t3 = B4.y; T.t4 = B4.z;
        } else {
            int c0 = w0 - 2 + 4 * q;
            T.t0 = ((unsigned)(c0 + 0) < WD) ? rowp[c0 + 0] : 0.0f;
            T.t1 = ((unsigned)(c0 + 1) < WD) ? rowp[c0 + 1] : 0.0f;
            T.t2 = ((unsigned)(c0 + 2) < WD) ? rowp[c0 + 2] : 0.0f;
            T.t3 = ((unsigned)(c0 + 3) < WD) ? rowp[c0 + 3] : 0.0f;
            T.t4 = ((unsigned)(c0 + 4) < WD) ? rowp[c0 + 4] : 0.0f;
        }
    }
}

// Store pairs 4q..4q+3 at swizzled index i(4q)=4q+2*(q>>1) (4 contiguous ulls).
__device__ __forceinline__ void store_task(ull (*spb)[SPR], int u, const Task& T)
{
    int row = u / 17;
    int q   = u - row * 17;
    ull* d = &spb[row][0] + 4 * q + 2 * (q >> 1);
    *reinterpret_cast<ulonglong2*>(d)     = make_ulonglong2(pk(T.t0, T.t1), pk(T.t1, T.t2));
    *reinterpret_cast<ulonglong2*>(d + 2) = make_ulonglong2(pk(T.t2, T.t3), pk(T.t3, T.t4));
}

// Accumulate one channel C from ring slot C&1. All indices compile-time.
template<int HALF, int C>
__device__ __forceinline__ void compute_channel(
    const Smem* s, ull acc[8][4], const ull* a0)
{
    const ull* a1 = a0 + 10;
#pragma unroll
    for (int dy = 0; dy < 5; dy++) {
        const int roff = dy * SPR;
        ulonglong2 L0 = *reinterpret_cast<const ulonglong2*>(a0 + roff);
        ulonglong2 L1 = *reinterpret_cast<const ulonglong2*>(a0 + roff + 2);
        ulonglong2 L2 = *reinterpret_cast<const ulonglong2*>(a0 + roff + 4);
        ulonglong2 L3 = *reinterpret_cast<const ulonglong2*>(a0 + roff + 6);
        ulonglong2 L4 = *reinterpret_cast<const ulonglong2*>(a1 + roff);
        ulonglong2 L5 = *reinterpret_cast<const ulonglong2*>(a1 + roff + 2);
        ull E[6] = { L0.x, L1.x, L2.x, L3.x, L4.x, L5.x };
        ull O[5] = { L0.y, L1.y, L2.y, L3.y, L4.y };

        const ull* w = s->wsm + ((HALF * CIN + C) * 5 + dy) * 30;
#pragma unroll
        for (int jj = 0; jj < 5; jj++) {
            ulonglong2 w01 = *reinterpret_cast<const ulonglong2*>(w + jj * 6);
            ulonglong2 w23 = *reinterpret_cast<const ulonglong2*>(w + jj * 6 + 2);
            ull        w4  = w[jj * 6 + 4];
            const int l = LIVEL[HALF][C][jj];
#pragma unroll
            for (int p = 0; p < 4; p++) {
                acc[l][p] = fma2(E[p],     w01.x, acc[l][p]);
                acc[l][p] = fma2(O[p],     w01.y, acc[l][p]);
                acc[l][p] = fma2(E[p + 1], w23.x, acc[l][p]);
                acc[l][p] = fma2(O[p + 1], w23.y, acc[l][p]);
                acc[l][p] = fma2(E[p + 2], w4,    acc[l][p]);
            }
        }
    }
}

template<int HALF>
__device__ __forceinline__ void dispatch_channel(
    int c, const Smem* s, ull acc[8][4], const ull* a0)
{
    switch (c) {
        case 0: compute_channel<HALF, 0>(s, acc, a0); break;
        case 1: compute_channel<HALF, 1>(s, acc, a0); break;
        case 2: compute_channel<HALF, 2>(s, acc, a0); break;
        case 3: compute_channel<HALF, 3>(s, acc, a0); break;
        case 4: compute_channel<HALF, 4>(s, acc, a0); break;
        default: compute_channel<HALF, 5>(s, acc, a0); break;
    }
}

template<int HALF>
__device__ __forceinline__ void init_acc(const Smem* s, ull acc[8][4])
{
#pragma unroll
    for (int l = 0; l < 8; l++) {
        float bv = s->sb[HC[HALF][l]];
        ull bb = pk(bv, bv);
#pragma unroll
        for (int p = 0; p < 4; p++) acc[l][p] = bb;
    }
}

template<int HALF>
__device__ __forceinline__ void epilogue(
    const ull acc[8][4], float* __restrict__ out,
    int b, int h0, int w0, int tx, int ty)
{
    const int hh = h0 + ty;
    const int ww = w0 + tx * PXT;
#pragma unroll
    for (int l = 0; l < 8; l++) {
        const int j = HC[HALF][l];
        ull* o = reinterpret_cast<ull*>(
            out + ((((size_t)b * COUT + j) * HT + hh) * WD + ww));
        *reinterpret_cast<ulonglong2*>(o)     = make_ulonglong2(acc[l][0], acc[l][1]);
        *reinterpret_cast<ulonglong2*>(o + 2) = make_ulonglong2(acc[l][2], acc[l][3]);
    }
}

__global__ __launch_bounds__(NT, 2)
void c3_conv_kernel(const float* __restrict__ x,
                    const float* __restrict__ Wt,
                    const float* __restrict__ bias,
                    float* __restrict__ out)
{
    extern __shared__ __align__(16) char smem_raw[];
    Smem* s = reinterpret_cast<Smem*>(smem_raw);

    const int tx = threadIdx.x, ty = threadIdx.y, tz = threadIdx.z;
    const int tid = tx + TX * ty + TX * TY * tz;

    // Stage weights ONCE per persistent CTA: duplicated (w,w) pairs,
    // [half][cin][dy][jj][dx pad 6].
    for (int i = tid; i < 2 * CIN * 5 * 5 * 5; i += NT) {
        int half = i / 750;
        int r = i - half * 750;
        int c  = r / 125; r -= c * 125;
        int dy = r / 25;  r -= dy * 25;
        int jj = r / 5;
        int dx = r - jj * 5;
        int j = d_LIVEG[half][c][jj];
        float wv = Wt[((j * CIN + c) * 5 + dy) * 5 + dx];
        s->wsm[(((half * CIN + c) * 5 + dy) * 5 + jj) * 6 + dx] = pk(wv, wv);
    }
    if (tid < COUT) s->sb[tid] = bias[tid];
    // first per-tile __syncthreads covers wsm/sb visibility

    // Read bases into the two ring slots (swizzle i(k)=k+2*(k>>3); pair 8tx -> 10tx).
    const ull* a0b[2] = { &s->sp[0][ty][0] + 10 * tx, &s->sp[1][ty][0] + 10 * tx };
    const bool two = (tid < NT2);

    for (int t = blockIdx.x; t < NTILE; t += NCTA) {
        const int wx = t & 7;
        const int hy = (t >> 3) & 31;
        const int b  = t >> 8;
        const int h0 = hy * TH;
        const int w0 = wx * TW;
        const float* xb = x + (size_t)b * CIN * HT * WD;

        // Prologue: build channel 0 into ring slot 0.
        {
            Task A; fetch_task(xb, 0, h0, w0, tid, A);
            Task B; if (two) fetch_task(xb, 0, h0, w0, NT + tid, B);
            store_task(s->sp[0], tid, A);
            if (two) store_task(s->sp[0], NT + tid, B);
        }
        __syncthreads();

        ull acc[8][4];
        if (tz == 0) init_acc<0>(s, acc); else init_acc<1>(s, acc);

        // Pipelined channel loop: LDG(c+1) -> compute(c) -> STS(c+1) -> sync.
#pragma unroll
        for (int c = 0; c < CIN; c++) {
            Task A;
            if (c + 1 < CIN) fetch_task(xb, c + 1, h0, w0, tid, A);

            if (tz == 0) dispatch_channel<0>(c, s, acc, a0b[c & 1]);
            else         dispatch_channel<1>(c, s, acc, a0b[c & 1]);

            if (c + 1 < CIN) {
                store_task(s->sp[(c + 1) & 1], tid, A);
                if (two) {
                    Task B; fetch_task(xb, c + 1, h0, w0, NT + tid, B);
                    store_task(s->sp[(c + 1) & 1], NT + tid, B);
                }
            }
            __syncthreads();
        }

        if (tz == 0) epilogue<0>(acc, out, b, h0, w0, tx, ty);
        else         epilogue<1>(acc, out, b, h0, w0, tx, ty);
    }
}

extern "C" void kernel_launch(void* const* d_in, const int* in_sizes, int n_in,
                              void* d_out, int out_size)
{
    (void)in_sizes; (void)n_in; (void)out_size;
    const float* x    = (const float*)d_in[0];
    const float* Wt   = (const float*)d_in[1];
    const float* bias = (const float*)d_in[2];
    // d_in[3] (mask) is the fixed LeNet C3 table, baked into the tables above.
    float* out = (float*)d_out;

    const int smem = (int)sizeof(Smem);
    cudaFuncSetAttribute(c3_conv_kernel,
                         cudaFuncAttributeMaxDynamicSharedMemorySize, smem);

    dim3 block(TX, TY, 2);
    dim3 grid(NCTA);
    c3_conv_kernel<<<grid, block, smem>>>(x, Wt, bias, out);
}

// round 15
// speedup vs baseline: 1.0488x; 1.0488x over previous
#include <cuda_runtime.h>

typedef unsigned long long ull;

#define CIN   6
#define COUT  16
#define HT    512
#define WD    512

#define TX    8           // threads.x
#define TY    16          // threads.y = tile height
#define PXT   8           // pixels per thread
#define TW    (TX*PXT)    // 64
#define TH    TY          // 16
#define SH    (TH+4)      // 20 halo rows
#define SPR   84          // swizzled pair row: i(k)=k+2*(k>>3)
#define NT    256
#define NTILE (8*32*32)   // 8192 tiles
#define NCTA  296         // 148 SMs * 2 CTAs
#define NTASK (SH*17)     // 340 build tasks per channel
#define NT2   (NTASK-NT)  // 84 threads carry a second task

__device__ __forceinline__ ull pk(float lo, float hi) {
    ull r; asm("mov.b64 %0,{%1,%2};" : "=l"(r) : "f"(lo), "f"(hi)); return r;
}
__device__ __forceinline__ ull fma2(ull a, ull b, ull c) {
    ull d; asm("fma.rn.f32x2 %0,%1,%2,%3;" : "=l"(d) : "l"(a), "l"(b), "l"(c)); return d;
}

// Balanced 2-coloring of the C3 table: every cin has exactly 5 live couts per half.
// half 0: {1,2,4,5,6,8,10,15}   half 1: {0,3,7,9,11,12,13,14}
__device__ const int d_LIVEG[2][CIN][5] = {
  {{4,5,6,10,15},{1,5,6,10,15},{1,2,6,8,15},{1,2,6,8,15},{2,4,8,10,15},{4,5,8,10,15}},
  {{0,9,11,12,14},{0,7,11,12,13},{0,7,11,13,14},{3,7,9,12,14},{3,7,9,12,13},{3,9,11,13,14}}};
__device__ constexpr int LIVEL[2][CIN][5] = {
  {{2,3,4,6,7},{0,3,4,6,7},{0,1,4,5,7},{0,1,4,5,7},{1,2,5,6,7},{2,3,5,6,7}},
  {{0,3,4,5,7},{0,2,4,5,6},{0,2,4,6,7},{1,2,3,5,7},{1,2,3,5,6},{1,3,4,6,7}}};
__device__ constexpr int HC[2][8] = {{1,2,4,5,6,8,10,15},{0,3,7,9,11,12,13,14}};

#define NWSM (2*CIN*5*5*6)   // [half][cin][dy][jj][dx pad6] = 1800 ulls

struct Smem {
    ull   sp[2][SH][SPR];   // 2-slot channel ring of interleaved pair rows (26.9 KB)
    ull   wsm[NWSM];        // duplicated weight pairs (14.4 KB)
    float sb[COUT];
};

struct Task { float t0, t1, t2, t3, t4; };

// Fetch taps t[4q..4q+4] of (channel c, halo row) — t[i] = x col (w0-2+i).
__device__ __forceinline__ void fetch_task(
    const float* __restrict__ xb, int c, int h0, int w0, int u, Task& T)
{
    int row = u / 17;
    int q   = u - row * 17;
    int gr  = h0 - 2 + row;
    T.t0 = T.t1 = T.t2 = T.t3 = T.t4 = 0.0f;
    if ((unsigned)gr < HT) {
        const float* rowp = xb + (size_t)c * HT * WD + (size_t)gr * WD;
        int ca = w0 - 4 + 4 * q;          // covers t[4q-2 .. 4q+5] via 2 LDG.128
        if (ca >= 0 && ca + 7 < WD) {
            float4 A4 = *reinterpret_cast<const float4*>(rowp + ca);
            float4 B4 = *reinterpret_cast<const float4*>(rowp + ca + 4);
            T.t0 = A4.z; T.t1 = A4.w; T.t2 = B4.x; T.t3 = B4.y; T.t4 = B4.z;
        } else {
            int c0 = w0 - 2 + 4 * q;
            T.t0 = ((unsigned)(c0 + 0) < WD) ? rowp[c0 + 0] : 0.0f;
            T.t1 = ((unsigned)(c0 + 1) < WD) ? rowp[c0 + 1] : 0.0f;
            T.t2 = ((unsigned)(c0 + 2) < WD) ? rowp[c0 + 2] : 0.0f;
            T.t3 = ((unsigned)(c0 + 3) < WD) ? rowp[c0 + 3] : 0.0f;
            T.t4 = ((unsigned)(c0 + 4) < WD) ? rowp[c0 + 4] : 0.0f;
        }
    }
}

// Store pairs 4q..4q+3 at swizzled index i(4q)=4q+2*(q>>1) (4 contiguous ulls).
__device__ __forceinline__ void store_task(ull (*spb)[SPR], int u, const Task& T)
{
    int row = u / 17;
    int q   = u - row * 17;
    ull* d = &spb[row][0] + 4 * q + 2 * (q >> 1);
    *reinterpret_cast<ulonglong2*>(d)     = make_ulonglong2(pk(T.t0, T.t1), pk(T.t1, T.t2));
    *reinterpret_cast<ulonglong2*>(d + 2) = make_ulonglong2(pk(T.t2, T.t3), pk(T.t3, T.t4));
}

// Accumulate one channel C from ring slot C&1. All indices compile-time.
template<int HALF, int C>
__device__ __forceinline__ void compute_channel(
    const Smem* s, ull acc[8][4], const ull* a0)
{
    const ull* a1 = a0 + 10;
#pragma unroll
    for (int dy = 0; dy < 5; dy++) {
        const int roff = dy * SPR;
        ulonglong2 L0 = *reinterpret_cast<const ulonglong2*>(a0 + roff);
        ulonglong2 L1 = *reinterpret_cast<const ulonglong2*>(a0 + roff + 2);
        ulonglong2 L2 = *reinterpret_cast<const ulonglong2*>(a0 + roff + 4);
        ulonglong2 L3 = *reinterpret_cast<const ulonglong2*>(a0 + roff + 6);
        ulonglong2 L4 = *reinterpret_cast<const ulonglong2*>(a1 + roff);
        ulonglong2 L5 = *reinterpret_cast<const ulonglong2*>(a1 + roff + 2);
        ull E[6] = { L0.x, L1.x, L2.x, L3.x, L4.x, L5.x };
        ull O[5] = { L0.y, L1.y, L2.y, L3.y, L4.y };

        const ull* w = s->wsm + ((HALF * CIN + C) * 5 + dy) * 30;
#pragma unroll
        for (int jj = 0; jj < 5; jj++) {
            ulonglong2 w01 = *reinterpret_cast<const ulonglong2*>(w + jj * 6);
            ulonglong2 w23 = *reinterpret_cast<const ulonglong2*>(w + jj * 6 + 2);
            ull        w4  = w[jj * 6 + 4];
            const int l = LIVEL[HALF][C][jj];
#pragma unroll
            for (int p = 0; p < 4; p++) {
                acc[l][p] = fma2(E[p],     w01.x, acc[l][p]);
                acc[l][p] = fma2(O[p],     w01.y, acc[l][p]);
                acc[l][p] = fma2(E[p + 1], w23.x, acc[l][p]);
                acc[l][p] = fma2(O[p + 1], w23.y, acc[l][p]);
                acc[l][p] = fma2(E[p + 2], w4,    acc[l][p]);
            }
        }
    }
}

template<int HALF>
__device__ __forceinline__ void dispatch_channel(
    int c, const Smem* s, ull acc[8][4], const ull* a0)
{
    switch (c) {
        case 0: compute_channel<HALF, 0>(s, acc, a0); break;
        case 1: compute_channel<HALF, 1>(s, acc, a0); break;
        case 2: compute_channel<HALF, 2>(s, acc, a0); break;
        case 3: compute_channel<HALF, 3>(s, acc, a0); break;
        case 4: compute_channel<HALF, 4>(s, acc, a0); break;
        default: compute_channel<HALF, 5>(s, acc, a0); break;
    }
}

template<int HALF>
__device__ __forceinline__ void init_acc(const Smem* s, ull acc[8][4])
{
#pragma unroll
    for (int l = 0; l < 8; l++) {
        float bv = s->sb[HC[HALF][l]];
        ull bb = pk(bv, bv);
#pragma unroll
        for (int p = 0; p < 4; p++) acc[l][p] = bb;
    }
}

template<int HALF>
__device__ __forceinline__ void epilogue(
    const ull acc[8][4], float* __restrict__ out,
    int b, int h0, int w0, int tx, int ty)
{
    const int hh = h0 + ty;
    const int ww = w0 + tx * PXT;
#pragma unroll
    for (int l = 0; l < 8; l++) {
        const int j = HC[HALF][l];
        ull* o = reinterpret_cast<ull*>(
            out + ((((size_t)b * COUT + j) * HT + hh) * WD + ww));
        *reinterpret_cast<ulonglong2*>(o)     = make_ulonglong2(acc[l][0], acc[l][1]);
        *reinterpret_cast<ulonglong2*>(o + 2) = make_ulonglong2(acc[l][2], acc[l][3]);
    }
}

__global__ __launch_bounds__(NT, 2)
void c3_conv_kernel(const float* __restrict__ x,
                    const float* __restrict__ Wt,
                    const float* __restrict__ bias,
                    float* __restrict__ out)
{
    extern __shared__ __align__(16) char smem_raw[];
    Smem* s = reinterpret_cast<Smem*>(smem_raw);

    const int tx = threadIdx.x, ty = threadIdx.y, tz = threadIdx.z;
    const int tid = tx + TX * ty + TX * TY * tz;

    // Stage weights ONCE per persistent CTA: duplicated (w,w) pairs,
    // [half][cin][dy][jj][dx pad 6].
    for (int i = tid; i < 2 * CIN * 5 * 5 * 5; i += NT) {
        int half = i / 750;
        int r = i - half * 750;
        int c  = r / 125; r -= c * 125;
        int dy = r / 25;  r -= dy * 25;
        int jj = r / 5;
        int dx = r - jj * 5;
        int j = d_LIVEG[half][c][jj];
        float wv = Wt[((j * CIN + c) * 5 + dy) * 5 + dx];
        s->wsm[(((half * CIN + c) * 5 + dy) * 5 + jj) * 6 + dx] = pk(wv, wv);
    }
    if (tid < COUT) s->sb[tid] = bias[tid];
    // first per-tile __syncthreads covers wsm/sb visibility

    // Read bases into the two ring slots (swizzle i(k)=k+2*(k>>3); pair 8tx -> 10tx).
    const ull* a0b[2] = { &s->sp[0][ty][0] + 10 * tx, &s->sp[1][ty][0] + 10 * tx };
    const bool two = (tid < NT2);

    for (int t = blockIdx.x; t < NTILE; t += NCTA) {
        const int wx = t & 7;
        const int hy = (t >> 3) & 31;
        const int b  = t >> 8;
        const int h0 = hy * TH;
        const int w0 = wx * TW;
        const float* xb = x + (size_t)b * CIN * HT * WD;

        // Prologue: build channel 0 into ring slot 0.
        {
            Task A; fetch_task(xb, 0, h0, w0, tid, A);
            Task B; if (two) fetch_task(xb, 0, h0, w0, NT + tid, B);
            store_task(s->sp[0], tid, A);
            if (two) store_task(s->sp[0], NT + tid, B);
        }
        __syncthreads();

        ull acc[8][4];
        if (tz == 0) init_acc<0>(s, acc); else init_acc<1>(s, acc);

        // Pipelined channel loop: LDG(c+1) -> compute(c) -> STS(c+1) -> sync.
#pragma unroll
        for (int c = 0; c < CIN; c++) {
            Task A;
            if (c + 1 < CIN) fetch_task(xb, c + 1, h0, w0, tid, A);

            if (tz == 0) dispatch_channel<0>(c, s, acc, a0b[c & 1]);
            else         dispatch_channel<1>(c, s, acc, a0b[c & 1]);

            if (c + 1 < CIN) {
                store_task(s->sp[(c + 1) & 1], tid, A);
                if (two) {
                    Task B; fetch_task(xb, c + 1, h0, w0, NT + tid, B);
                    store_task(s->sp[(c + 1) & 1], NT + tid, B);
                }
            }
            __syncthreads();
        }

        if (tz == 0) epilogue<0>(acc, out, b, h0, w0, tx, ty);
        else         epilogue<1>(acc, out, b, h0, w0, tx, ty);
    }
}

extern "C" void kernel_launch(void* const* d_in, const int* in_sizes, int n_in,
                              void* d_out, int out_size)
{
    (void)in_sizes; (void)n_in; (void)out_size;
    const float* x    = (const float*)d_in[0];
    const float* Wt   = (const float*)d_in[1];
    const float* bias = (const float*)d_in[2];
    // d_in[3] (mask) is the fixed LeNet C3 table, baked into the tables above.
    float* out = (float*)d_out;

    const int smem = (int)sizeof(Smem);
    cudaFuncSetAttribute(c3_conv_kernel,
                         cudaFuncAttributeMaxDynamicSharedMemorySize, smem);

    dim3 block(TX, TY, 2);
    dim3 grid(NCTA);
    c3_conv_kernel<<<grid, block, smem>>>(x, Wt, bias, out);
}

// round 16
// speedup vs baseline: 1.2138x; 1.1573x over previous
#include <cuda_runtime.h>

typedef unsigned long long ull;

#define CIN   6
#define COUT  16
#define HT    512
#define WD    512

#define TX    8           // threads.x
#define TY    16          // threads.y = tile height
#define PXT   8           // pixels per thread
#define TW    (TX*PXT)    // 64
#define TH    TY          // 16
#define SH    (TH+4)      // 20 halo rows
#define SPR   84          // swizzled pair row: i(k)=k+2*(k>>3)
#define NT    256
#define NTILE (8*32*32)   // 8192 tiles
#define NCTA  296         // 148 SMs * 2 CTAs

#define NWSM (2*CIN*5*5*6)   // [half][cin][dy][jj][dx pad6] = 1800 ulls

__device__ __forceinline__ ull pk(float lo, float hi) {
    ull r; asm("mov.b64 %0,{%1,%2};" : "=l"(r) : "f"(lo), "f"(hi)); return r;
}
__device__ __forceinline__ ull fma2(ull a, ull b, ull c) {
    ull d; asm("fma.rn.f32x2 %0,%1,%2,%3;" : "=l"(d) : "l"(a), "l"(b), "l"(c)); return d;
}

// Balanced 2-coloring of the C3 table: every cin has exactly 5 live couts per half.
// half 0: {1,2,4,5,6,8,10,15}   half 1: {0,3,7,9,11,12,13,14}
__device__ const int d_LIVEG[2][CIN][5] = {
  {{4,5,6,10,15},{1,5,6,10,15},{1,2,6,8,15},{1,2,6,8,15},{2,4,8,10,15},{4,5,8,10,15}},
  {{0,9,11,12,14},{0,7,11,12,13},{0,7,11,13,14},{3,7,9,12,14},{3,7,9,12,13},{3,9,11,13,14}}};
__device__ constexpr int LIVEL[2][CIN][5] = {
  {{2,3,4,6,7},{0,3,4,6,7},{0,1,4,5,7},{0,1,4,5,7},{1,2,5,6,7},{2,3,5,6,7}},
  {{0,3,4,5,7},{0,2,4,5,6},{0,2,4,6,7},{1,2,3,5,7},{1,2,3,5,6},{1,3,4,6,7}}};
__device__ constexpr int HC[2][8] = {{1,2,4,5,6,8,10,15},{0,3,7,9,11,12,13,14}};

// Weights/bias live in the constant bank during the main kernel.
__constant__ ull   cwsm[NWSM];
__constant__ float csb[COUT];

// Prep scratch (device globals — no allocation).
__device__ ull   g_wscr[NWSM];
__device__ float g_bscr[COUT];

// Expand W into duplicated (w,w) pairs, layout [half][cin][dy][jj][dx pad 6].
__global__ void prep_kernel(const float* __restrict__ Wt,
                            const float* __restrict__ bias)
{
    int i = blockIdx.x * blockDim.x + threadIdx.x;
    if (i < COUT) g_bscr[i] = bias[i];
    if (i >= NWSM) return;
    int half = i / 900;
    int r = i - half * 900;
    int c  = r / 150; r -= c * 150;
    int dy = r / 30;  r -= dy * 30;
    int jj = r / 6;
    int dx = r - jj * 6;
    float wv = 0.0f;
    if (dx < 5) {
        int j = d_LIVEG[half][c][jj];
        wv = Wt[((j * CIN + c) * 5 + dy) * 5 + dx];
    }
    g_wscr[i] = pk(wv, wv);
}

struct Smem {
    ull sp[CIN][SH][SPR];   // interleaved pair tile, swizzled (80.6 KB)
};

template<int HALF>
__device__ __forceinline__ void compute_half(
    const Smem* s, float* __restrict__ out,
    int b, int h0, int w0, int tx, int ty)
{
    ull acc[8][4];
#pragma unroll
    for (int l = 0; l < 8; l++) {
        float bv = csb[HC[HALF][l]];          // immediate const-bank load
        ull bb = pk(bv, bv);
#pragma unroll
        for (int p = 0; p < 4; p++) acc[l][p] = bb;
    }

    // Swizzle i(k)=k+2*(k>>3): pair elem 8*tx -> index 10*tx; both bases
    // conflict-free per 8-lane phase, all reads contiguous LDS.128.
    const ull* a0 = &s->sp[0][ty][0] + 10 * tx;
    const ull* a1 = a0 + 10;

#pragma unroll
    for (int c = 0; c < CIN; c++) {
#pragma unroll
        for (int dy = 0; dy < 5; dy++) {
            const int roff = (c * SH + dy) * SPR;    // immediate after unroll
            ulonglong2 L0 = *reinterpret_cast<const ulonglong2*>(a0 + roff);
            ulonglong2 L1 = *reinterpret_cast<const ulonglong2*>(a0 + roff + 2);
            ulonglong2 L2 = *reinterpret_cast<const ulonglong2*>(a0 + roff + 4);
            ulonglong2 L3 = *reinterpret_cast<const ulonglong2*>(a0 + roff + 6);
            ulonglong2 L4 = *reinterpret_cast<const ulonglong2*>(a1 + roff);
            ulonglong2 L5 = *reinterpret_cast<const ulonglong2*>(a1 + roff + 2);
            ull E[6] = { L0.x, L1.x, L2.x, L3.x, L4.x, L5.x };
            ull O[5] = { L0.y, L1.y, L2.y, L3.y, L4.y };

            // Weight pairs from the constant bank — compile-time offsets.
            const ull* w = cwsm + ((HALF * CIN + c) * 5 + dy) * 30;
#pragma unroll
            for (int jj = 0; jj < 5; jj++) {
                ull w0v = w[jj * 6 + 0];
                ull w1v = w[jj * 6 + 1];
                ull w2v = w[jj * 6 + 2];
                ull w3v = w[jj * 6 + 3];
                ull w4v = w[jj * 6 + 4];
                const int l = LIVEL[HALF][c][jj];
#pragma unroll
                for (int p = 0; p < 4; p++) {
                    acc[l][p] = fma2(E[p],     w0v, acc[l][p]);
                    acc[l][p] = fma2(O[p],     w1v, acc[l][p]);
                    acc[l][p] = fma2(E[p + 1], w2v, acc[l][p]);
                    acc[l][p] = fma2(O[p + 1], w3v, acc[l][p]);
                    acc[l][p] = fma2(E[p + 2], w4v, acc[l][p]);
                }
            }
        }
    }

    // Accumulator pairs are (out[2p], out[2p+1]) -> direct STG.128.
    const int hh = h0 + ty;
    const int ww = w0 + tx * PXT;
#pragma unroll
    for (int l = 0; l < 8; l++) {
        const int j = HC[HALF][l];
        ull* o = reinterpret_cast<ull*>(
            out + ((((size_t)b * COUT + j) * HT + hh) * WD + ww));
        *reinterpret_cast<ulonglong2*>(o)     = make_ulonglong2(acc[l][0], acc[l][1]);
        *reinterpret_cast<ulonglong2*>(o + 2) = make_ulonglong2(acc[l][2], acc[l][3]);
    }
}

__global__ __launch_bounds__(NT, 2)
void c3_conv_kernel(const float* __restrict__ x,
                    float* __restrict__ out)
{
    extern __shared__ __align__(16) char smem_raw[];
    Smem* s = reinterpret_cast<Smem*>(smem_raw);

    const int tx = threadIdx.x, ty = threadIdx.y, tz = threadIdx.z;
    const int tid = tx + TX * ty + TX * TY * tz;

    for (int t = blockIdx.x; t < NTILE; t += NCTA) {
        const int wx = t & 7;
        const int hy = (t >> 3) & 31;
        const int b  = t >> 8;
        const int h0 = hy * TH;
        const int w0 = wx * TW;
        const float* xb = x + (size_t)b * CIN * HT * WD;

        // Monolithic tile build (R9 structure): task (c,row,q) builds pairs
        // 4q..4q+3 of sp[c][row] from taps t[4q..4q+4], t[i] = x col (w0-2+i).
        // All channels' LDGs in flight together -> one latency exposure per tile.
        for (int u = tid; u < CIN * SH * 17; u += NT) {
            int c   = u / (SH * 17);
            int r2  = u - c * (SH * 17);
            int row = r2 / 17;
            int q   = r2 - row * 17;
            int gr  = h0 - 2 + row;
            float t0, t1, t2, t3, t4;
            if ((unsigned)gr < HT) {
                const float* rowp = xb + (size_t)c * HT * WD + (size_t)gr * WD;
                int ca = w0 - 4 + 4 * q;   // 2 LDG.128 cover t[4q-2..4q+5]
                if (ca >= 0 && ca + 7 < WD) {
                    float4 A4 = *reinterpret_cast<const float4*>(rowp + ca);
                    float4 B4 = *reinterpret_cast<const float4*>(rowp + ca + 4);
                    t0 = A4.z; t1 = A4.w; t2 = B4.x; t3 = B4.y; t4 = B4.z;
                } else {
                    int c0 = w0 - 2 + 4 * q;
                    t0 = ((unsigned)(c0 + 0) < WD) ? rowp[c0 + 0] : 0.0f;
                    t1 = ((unsigned)(c0 + 1) < WD) ? rowp[c0 + 1] : 0.0f;
                    t2 = ((unsigned)(c0 + 2) < WD) ? rowp[c0 + 2] : 0.0f;
                    t3 = ((unsigned)(c0 + 3) < WD) ? rowp[c0 + 3] : 0.0f;
                    t4 = ((unsigned)(c0 + 4) < WD) ? rowp[c0 + 4] : 0.0f;
                }
            } else {
                t0 = t1 = t2 = t3 = t4 = 0.0f;
            }
            // swizzled write index i(4q) = 4q + 2*(q>>1); 4 pairs contiguous
            ull* d = &s->sp[c][row][0] + 4 * q + 2 * (q >> 1);
            *reinterpret_cast<ulonglong2*>(d)     = make_ulonglong2(pk(t0, t1), pk(t1, t2));
            *reinterpret_cast<ulonglong2*>(d + 2) = make_ulonglong2(pk(t2, t3), pk(t3, t4));
        }
        __syncthreads();

        if (tz == 0) compute_half<0>(s, out, b, h0, w0, tx, ty);
        else         compute_half<1>(s, out, b, h0, w0, tx, ty);
        __syncthreads();   // protect sp before next tile's build
    }
}

extern "C" void kernel_launch(void* const* d_in, const int* in_sizes, int n_in,
                              void* d_out, int out_size)
{
    (void)in_sizes; (void)n_in; (void)out_size;
    const float* x    = (const float*)d_in[0];
    const float* Wt   = (const float*)d_in[1];
    const float* bias = (const float*)d_in[2];
    // d_in[3] (mask) is the fixed LeNet C3 table, baked into the tables above.
    float* out = (float*)d_out;

    // Stage weights into the constant bank: prep kernel -> D2D memcpy to symbol.
    // Both are graph-capturable stream ops (no allocation, no sync).
    prep_kernel<<<8, 256>>>(Wt, bias);
    void* wsrc = nullptr; void* bsrc = nullptr;
    cudaGetSymbolAddress(&wsrc, g_wscr);
    cudaGetSymbolAddress(&bsrc, g_bscr);
    cudaMemcpyToSymbolAsync(cwsm, wsrc, sizeof(ull) * NWSM, 0,
                            cudaMemcpyDeviceToDevice);
    cudaMemcpyToSymbolAsync(csb, bsrc, sizeof(float) * COUT, 0,
                            cudaMemcpyDeviceToDevice);

    const int smem = (int)sizeof(Smem);
    cudaFuncSetAttribute(c3_conv_kernel,
                         cudaFuncAttributeMaxDynamicSharedMemorySize, smem);

    dim3 block(TX, TY, 2);
    dim3 grid(NCTA);
    c3_conv_kernel<<<grid, block, smem>>>(x, out);
}